// round 4
// baseline (speedup 1.0000x reference)
#include <cuda_runtime.h>
#include <cuda_bf16.h>

// upfirdn2d: up=2, down=1, pad=(2,1), 4x4 separable FIR (rank-1: K = g x f).
// Input 2048 planes of 128x128 f32 -> Output 2048 planes of 256x256 f32.
//
// Per-dim half-phase taps (true conv on zero-inserted, padded signal):
//   even o: f[3]*x[o/2-1] + f[1]*x[o/2]
//   odd  o: f[2]*x[(o-1)/2] + f[0]*x[(o+1)/2]
// Horizontal half-conv per input row -> h[8] per lane, then vertical combine:
//   out row 2r   = g3*h(r-1) + h(r)          (g1 normalized to 1)
//   out row 2r+1 = g2*h(r)   + g0*h(r+1)
//
// One warp spans a FULL input row (32 lanes x float4 = 128 cols): horizontal
// halo is pure warp-shuffle; lanes 0/31 see the true zero pad. Each warp
// rolls down 8 rows with a one-row raw prefetch to decouple LDG latency
// from the store stream. 2 blocks per plane for wave balance.

#define H   128
#define W   128
#define OW  256
#define RPW 8    // input rows per warp

__global__ __launch_bounds__(256) void fir_up2_kernel(
    const float* __restrict__ x,
    const float* __restrict__ kern,
    float* __restrict__ out)
{
    const int plane = blockIdx.y;
    const int warp  = threadIdx.x >> 5;
    const int lane  = threadIdx.x & 31;
    const int r0    = blockIdx.x * (8 * RPW) + warp * RPW;  // strip start row
    const int c0    = lane * 4;

    const float* __restrict__ xp = x + (size_t)plane * (H * W);
    float* __restrict__ op = out + (size_t)plane * (OW * 2 * H);

    // taps (rank-1 factorization of the 4x4 kernel)
    const float f0 = __ldg(kern + 4 + 0);
    const float f1 = __ldg(kern + 4 + 1);
    const float f2 = __ldg(kern + 4 + 2);
    const float f3 = __ldg(kern + 4 + 3);
    const float inv = 1.0f / f1;
    const float g0 = __ldg(kern + 0 * 4 + 1) * inv;
    const float g2 = __ldg(kern + 2 * 4 + 1) * inv;
    const float g3 = __ldg(kern + 3 * 4 + 1) * inv;

    // Raw full-row load (LDG.128 per lane); zeros outside [0,H).
    auto load_raw = [&](int r) -> float4 {
        if (r < 0 || r >= H) return make_float4(0.f, 0.f, 0.f, 0.f);
        return __ldcs((const float4*)(xp + r * W + c0));
    };

    // Horizontal half-convolution of one raw row -> 8 output-col values.
    auto hconv = [&](float4 v, float h[8]) {
        float m = __shfl_up_sync(0xffffffffu, v.w, 1);
        if (lane == 0) m = 0.0f;               // true left zero-pad
        float q = __shfl_down_sync(0xffffffffu, v.x, 1);
        if (lane == 31) q = 0.0f;              // true right zero-pad
        h[0] = f3 * m   + f1 * v.x;
        h[1] = f2 * v.x + f0 * v.y;
        h[2] = f3 * v.x + f1 * v.y;
        h[3] = f2 * v.y + f0 * v.z;
        h[4] = f3 * v.y + f1 * v.z;
        h[5] = f2 * v.z + f0 * v.w;
        h[6] = f3 * v.z + f1 * v.w;
        h[7] = f2 * v.w + f0 * q;
    };

    float hprev[8], hcur[8], hnxt[8];
    hconv(load_raw(r0 - 1), hprev);
    hconv(load_raw(r0),     hcur);
    float4 vnxt = load_raw(r0 + 1);   // prefetched raw row r+1

    const int oc = 8 * lane;

#pragma unroll 4
    for (int i = 0; i < RPW; i++) {
        const int r = r0 + i;
        float4 vn2 = load_raw(r + 2);   // prefetch next-next row early
        hconv(vnxt, hnxt);

        float4 e0, e1, o0, o1;
        e0.x = g3 * hprev[0] + hcur[0];
        e0.y = g3 * hprev[1] + hcur[1];
        e0.z = g3 * hprev[2] + hcur[2];
        e0.w = g3 * hprev[3] + hcur[3];
        e1.x = g3 * hprev[4] + hcur[4];
        e1.y = g3 * hprev[5] + hcur[5];
        e1.z = g3 * hprev[6] + hcur[6];
        e1.w = g3 * hprev[7] + hcur[7];
        o0.x = g2 * hcur[0] + g0 * hnxt[0];
        o0.y = g2 * hcur[1] + g0 * hnxt[1];
        o0.z = g2 * hcur[2] + g0 * hnxt[2];
        o0.w = g2 * hcur[3] + g0 * hnxt[3];
        o1.x = g2 * hcur[4] + g0 * hnxt[4];
        o1.y = g2 * hcur[5] + g0 * hnxt[5];
        o1.z = g2 * hcur[6] + g0 * hnxt[6];
        o1.w = g2 * hcur[7] + g0 * hnxt[7];

        float* re = op + (size_t)(2 * r) * OW + oc;
        float* ro = op + (size_t)(2 * r + 1) * OW + oc;
        __stcs((float4*)(re),     e0);
        __stcs((float4*)(re + 4), e1);
        __stcs((float4*)(ro),     o0);
        __stcs((float4*)(ro + 4), o1);

#pragma unroll
        for (int j = 0; j < 8; j++) { hprev[j] = hcur[j]; hcur[j] = hnxt[j]; }
        vnxt = vn2;
    }
}

extern "C" void kernel_launch(void* const* d_in, const int* in_sizes, int n_in,
                              void* d_out, int out_size) {
    const float* x = (const float*)d_in[0];
    const float* k = (const float*)d_in[1];
    float* out = (float*)d_out;

    const int planes = in_sizes[0] / (H * W);   // 2048
    dim3 grid(2, planes);                        // 2 strips x 2048 planes
    fir_up2_kernel<<<grid, 256>>>(x, k, out);
}

// round 5
// speedup vs baseline: 1.0440x; 1.0440x over previous
#include <cuda_runtime.h>
#include <cuda_bf16.h>

// upfirdn2d: up=2, down=1, pad=(2,1), 4x4 separable FIR (rank-1: K = g x f).
// Input 2048 planes of 128x128 f32 -> Output 2048 planes of 256x256 f32.
//
// Per-dim half-phase taps (true conv on zero-inserted, padded signal):
//   even o: f[3]*x[o/2-1] + f[1]*x[o/2]
//   odd  o: f[2]*x[(o-1)/2] + f[0]*x[(o+1)/2]
// Horizontal half-conv per input row -> h[8] per lane, then vertical combine:
//   out row 2r   = g3*h(r-1) + h(r)          (g1 normalized to 1)
//   out row 2r+1 = g2*h(r)   + g0*h(r+1)
//
// One warp spans a FULL input row (32 lanes x float4 = 128 cols): horizontal
// halo is pure warp-shuffle; lanes 0/31 see the true zero pad. Each warp
// rolls down 16 rows, loading each input row exactly once.
// 128-thread blocks (4 warps = 64 rows) for finer tail granularity.

#define H   128
#define W   128
#define OW  256
#define RPW 16   // input rows per warp

__global__ __launch_bounds__(128) void fir_up2_kernel(
    const float* __restrict__ x,
    const float* __restrict__ kern,
    float* __restrict__ out)
{
    const int plane = blockIdx.y;
    const int warp  = threadIdx.x >> 5;
    const int lane  = threadIdx.x & 31;
    const int r0    = blockIdx.x * 64 + warp * RPW;   // 2 blocks x 4 warps x 16
    const int c0    = lane * 4;                       // input col of v.x

    const float* __restrict__ xp = x + (size_t)plane * (H * W);
    float* __restrict__ op = out + (size_t)plane * (OW * 2 * H);

    // taps (rank-1 factorization of the 4x4 kernel)
    const float f0 = __ldg(kern + 4 + 0);
    const float f1 = __ldg(kern + 4 + 1);
    const float f2 = __ldg(kern + 4 + 2);
    const float f3 = __ldg(kern + 4 + 3);
    const float inv = 1.0f / f1;
    const float g0 = __ldg(kern + 0 * 4 + 1) * inv;
    const float g2 = __ldg(kern + 2 * 4 + 1) * inv;
    const float g3 = __ldg(kern + 3 * 4 + 1) * inv;

    // Load one full input row (LDG.128/lane) + horizontal half-conv -> h[8].
    auto loadh = [&](int r, float h[8]) {
        if (r < 0 || r >= H) {
#pragma unroll
            for (int j = 0; j < 8; j++) h[j] = 0.0f;
            return;
        }
        float4 v = *(const float4*)(xp + r * W + c0);
        float m = __shfl_up_sync(0xffffffffu, v.w, 1);
        if (lane == 0) m = 0.0f;               // true left zero-pad
        float q = __shfl_down_sync(0xffffffffu, v.x, 1);
        if (lane == 31) q = 0.0f;              // true right zero-pad
        h[0] = f3 * m   + f1 * v.x;
        h[1] = f2 * v.x + f0 * v.y;
        h[2] = f3 * v.x + f1 * v.y;
        h[3] = f2 * v.y + f0 * v.z;
        h[4] = f3 * v.y + f1 * v.z;
        h[5] = f2 * v.z + f0 * v.w;
        h[6] = f3 * v.z + f1 * v.w;
        h[7] = f2 * v.w + f0 * q;
    };

    float hprev[8], hcur[8], hnxt[8];
    loadh(r0 - 1, hprev);
    loadh(r0,     hcur);

    const int oc = 8 * lane;   // output col base (float4-aligned)

#pragma unroll 4
    for (int i = 0; i < RPW; i++) {
        const int r = r0 + i;
        loadh(r + 1, hnxt);

        float4 e0, e1, o0, o1;
        e0.x = g3 * hprev[0] + hcur[0];
        e0.y = g3 * hprev[1] + hcur[1];
        e0.z = g3 * hprev[2] + hcur[2];
        e0.w = g3 * hprev[3] + hcur[3];
        e1.x = g3 * hprev[4] + hcur[4];
        e1.y = g3 * hprev[5] + hcur[5];
        e1.z = g3 * hprev[6] + hcur[6];
        e1.w = g3 * hprev[7] + hcur[7];
        o0.x = g2 * hcur[0] + g0 * hnxt[0];
        o0.y = g2 * hcur[1] + g0 * hnxt[1];
        o0.z = g2 * hcur[2] + g0 * hnxt[2];
        o0.w = g2 * hcur[3] + g0 * hnxt[3];
        o1.x = g2 * hcur[4] + g0 * hnxt[4];
        o1.y = g2 * hcur[5] + g0 * hnxt[5];
        o1.z = g2 * hcur[6] + g0 * hnxt[6];
        o1.w = g2 * hcur[7] + g0 * hnxt[7];

        float* re = op + (size_t)(2 * r) * OW + oc;
        float* ro = op + (size_t)(2 * r + 1) * OW + oc;
        __stcs((float4*)(re),     e0);
        __stcs((float4*)(re + 4), e1);
        __stcs((float4*)(ro),     o0);
        __stcs((float4*)(ro + 4), o1);

#pragma unroll
        for (int j = 0; j < 8; j++) { hprev[j] = hcur[j]; hcur[j] = hnxt[j]; }
    }
}

extern "C" void kernel_launch(void* const* d_in, const int* in_sizes, int n_in,
                              void* d_out, int out_size) {
    const float* x = (const float*)d_in[0];
    const float* k = (const float*)d_in[1];
    float* out = (float*)d_out;

    const int planes = in_sizes[0] / (H * W);   // 2048
    dim3 grid(2, planes);                        // 2 half-plane blocks x 2048
    fir_up2_kernel<<<grid, 128>>>(x, k, out);
}